// round 3
// baseline (speedup 1.0000x reference)
#include <cuda_runtime.h>

#define NN 32
#define SUU 8
#define HHH 64
#define NCC 4
#define EEE 992
#define NITER 5

struct __align__(16) Smem {
    // float4-accessed arrays first (16B alignment)
    float W2b[32 * 64];    // [c][k]
    float W2cT[32 * 8];    // [c][o]  (transposed W2c)
    float A[32 * 65];      // per-node source-part, padded stride 65 (conflict-free gather)
    float C[32 * 64];      // per-node target-part + noise + bias
    float W2a[64 * 18];    // full layer-1 weight
    float WhhT[64 * 193];  // transposed Whh, stride 193 (also reused as staging in final phase)
    float WihT[10 * 193];  // transposed Wih, stride 193
    float hid[32 * 64];    // GRU hidden state
    float W4[8 * 65];      // padded stride 65
    float ew[992];         // edge weights for this batch
    float inn[32 * 8];     // init_nodes
    float rg[32 * 8];      // read_gru state
    float xv[64];          // x_hat, variance interleaved per node
    float b2a[64];
    float b2b[32];
    float bih[192];
    float bhh[192];
    float b2c[8];
    float b1a[8];
    float b4[8];
    float W1a[24];
};

struct Params {
    const float* read_gru; const float* gru_init; const float* feat; const float* ew;
    const float* noise; const float* xh; const float* var;
    const float* W1a; const float* b1a;
    const float* W2a; const float* b2a; const float* W2b; const float* b2b;
    const float* W2c; const float* b2c;
    const float* Wih; const float* bih; const float* Whh; const float* bhh;
    const float* W3a; const float* b3a; const float* W3b; const float* b3b;
    const float* W3c; const float* b3c;
    const float* W4; const float* b4;
    const int* gnn;
    float* out;
    int B;
};

__device__ __forceinline__ float sigf(float x) {
    return 1.0f / (1.0f + __expf(-x));
}
// overflow-safe accurate tanh via __expf
__device__ __forceinline__ float tanh_acc(float x) {
    float a = fabsf(x);
    float e = __expf(-2.0f * a);           // in (0, 1], never overflows
    float t = (1.0f - e) / (1.0f + e);
    return copysignf(t, x);
}

__global__ void __launch_bounds__(256, 2) gnn_kernel(Params p) {
    extern __shared__ char smem_raw[];
    Smem& S = *reinterpret_cast<Smem*>(smem_raw);
    const int b = blockIdx.x;
    const int tid = threadIdx.x;
    const int w = tid >> 5, l = tid & 31;

    // ---------------- Phase 0: stage everything into smem ----------------
    for (int i = tid; i < 64 * 18; i += 256) S.W2a[i] = p.W2a[i];
    for (int i = tid; i < 2048; i += 256) S.W2b[i] = p.W2b[i];
    {   // W2c (8,32) -> W2cT[c][o]
        int c = tid >> 3, o = tid & 7;
        S.W2cT[tid] = p.W2c[o * 32 + c];
    }
    for (int i = tid; i < 12288; i += 256) {   // Whh (192,64) -> WhhT[k][g], stride 193
        int g = i >> 6, k = i & 63;
        S.WhhT[k * 193 + g] = p.Whh[i];
    }
    for (int i = tid; i < 1920; i += 256) {    // Wih (192,10) -> WihT[k][g], stride 193
        int g = i / 10, k = i - g * 10;
        S.WihT[k * 193 + g] = p.Wih[i];
    }
    for (int i = tid; i < 2048; i += 256) S.hid[i] = p.gru_init[b * 2048 + i];
    for (int i = tid; i < 992; i += 256) S.ew[i] = p.ew[b * 992 + i];
    for (int i = tid; i < 512; i += 256) {     // W4 (8,64) padded
        int s = i >> 6, k = i & 63;
        S.W4[s * 65 + k] = p.W4[i];
    }
    S.rg[tid] = p.read_gru[b * 256 + tid];
    if (tid < 192) { S.bih[tid] = p.bih[tid]; S.bhh[tid] = p.bhh[tid]; }
    if (tid < 64) S.b2a[tid] = p.b2a[tid];
    if (tid < 32) {
        S.b2b[tid] = p.b2b[tid];
        S.xv[2 * tid]     = p.xh[b * 32 + tid];
        S.xv[2 * tid + 1] = p.var[b * 32 + tid];
    }
    if (tid < 24) S.W1a[tid] = p.W1a[tid];
    if (tid < 8) { S.b2c[tid] = p.b2c[tid]; S.b1a[tid] = p.b1a[tid]; S.b4[tid] = p.b4[tid]; }
    const float noise = p.noise[b];
    const int gnn = p.gnn[0];
    __syncthreads();

    // ---------------- Main iterations ----------------
    for (int it = 0; it < NITER; ++it) {
        // Phase 1: init_nodes
        {
            int j = tid >> 3, s = tid & 7;
            float v;
            if (it == 0 && gnn == 0) {
                const float* f = p.feat + (b * 32 + j) * 3;
                v = S.b1a[s];
                v = fmaf(f[0], S.W1a[s * 3 + 0], v);
                v = fmaf(f[1], S.W1a[s * 3 + 1], v);
                v = fmaf(f[2], S.W1a[s * 3 + 2], v);
            } else {
                v = S.rg[tid];
            }
            S.inn[tid] = v;
        }
        __syncthreads();

        // Phase 2: per-node A (source part) and C (target part + noise + bias)
        for (int i = tid; i < 2048; i += 256) {
            int a = i >> 6, o = i & 63;
            const float* wr = &S.W2a[o * 18];
            const float* xn = &S.inn[a * 8];
            float va = 0.f;
            float vc = fmaf(noise, wr[17], S.b2a[o]);
            #pragma unroll
            for (int s = 0; s < 8; ++s) {
                va = fmaf(xn[s], wr[s], va);
                vc = fmaf(xn[s], wr[8 + s], vc);
            }
            S.A[a * 65 + o] = va;
            S.C[a * 64 + o] = vc;
        }
        __syncthreads();

        // Phase 3+4 fused: warp-per-target-node edge MLP + message sum + GRU
        for (int r = 0; r < 4; ++r) {
            const int j = w * 4 + r;
            const bool act = (l < 31);
            int a = l + (l >= j ? 1 : 0);
            if (a > 31) a = 31;                 // lane 31 reads dummy, result zeroed
            const float ewv = act ? S.ew[j * 31 + l] : 0.f;

            // layer 1 (factored): m1[o] = relu(C[j][o] + ew*W2a[o][16] + A[a][o])
            float m1[64];
            #pragma unroll
            for (int o = 0; o < 64; ++o) {
                float pre = fmaf(ewv, S.W2a[o * 18 + 16], S.C[j * 64 + o]) + S.A[a * 65 + o];
                m1[o] = fmaxf(pre, 0.f);
            }

            // layers 2+3 fused; layer-3 relu applied after full dot
            float acc[8];
            #pragma unroll
            for (int o = 0; o < 8; ++o) acc[o] = S.b2c[o];
            #pragma unroll 1
            for (int c = 0; c < 32; ++c) {
                const float4* wrow = reinterpret_cast<const float4*>(&S.W2b[c * 64]);
                float t0 = S.b2b[c], t1 = 0.f, t2 = 0.f, t3 = 0.f;
                #pragma unroll
                for (int k4 = 0; k4 < 16; ++k4) {
                    float4 ww = wrow[k4];
                    t0 = fmaf(m1[4 * k4 + 0], ww.x, t0);
                    t1 = fmaf(m1[4 * k4 + 1], ww.y, t1);
                    t2 = fmaf(m1[4 * k4 + 2], ww.z, t2);
                    t3 = fmaf(m1[4 * k4 + 3], ww.w, t3);
                }
                float t = fmaxf((t0 + t1) + (t2 + t3), 0.f);
                float4 u0 = reinterpret_cast<const float4*>(&S.W2cT[c * 8])[0];
                float4 u1 = reinterpret_cast<const float4*>(&S.W2cT[c * 8])[1];
                acc[0] = fmaf(t, u0.x, acc[0]); acc[1] = fmaf(t, u0.y, acc[1]);
                acc[2] = fmaf(t, u0.z, acc[2]); acc[3] = fmaf(t, u0.w, acc[3]);
                acc[4] = fmaf(t, u1.x, acc[4]); acc[5] = fmaf(t, u1.y, acc[5]);
                acc[6] = fmaf(t, u1.z, acc[6]); acc[7] = fmaf(t, u1.w, acc[7]);
            }
            // per-edge relu (layer 3), zero inactive lane
            #pragma unroll
            for (int o = 0; o < 8; ++o) acc[o] = act ? fmaxf(acc[o], 0.f) : 0.f;

            // butterfly sum over 31 edges -> full result in every lane
            #pragma unroll
            for (int off = 16; off >= 1; off >>= 1) {
                #pragma unroll
                for (int o = 0; o < 8; ++o)
                    acc[o] += __shfl_xor_sync(0xFFFFFFFFu, acc[o], off);
            }

            // ---- GRU for node j (lane l owns output channels g = 32p + l) ----
            const float xh = S.xv[2 * j], vv = S.xv[2 * j + 1];
            float ai[6], ah[6];
            #pragma unroll
            for (int pp = 0; pp < 6; ++pp) {
                ai[pp] = S.bih[32 * pp + l];
                ah[pp] = S.bhh[32 * pp + l];
            }
            #pragma unroll
            for (int k = 0; k < 8; ++k) {
                float g = acc[k];
                #pragma unroll
                for (int pp = 0; pp < 6; ++pp)
                    ai[pp] = fmaf(g, S.WihT[k * 193 + 32 * pp + l], ai[pp]);
            }
            #pragma unroll
            for (int pp = 0; pp < 6; ++pp) {
                ai[pp] = fmaf(xh, S.WihT[8 * 193 + 32 * pp + l], ai[pp]);
                ai[pp] = fmaf(vv, S.WihT[9 * 193 + 32 * pp + l], ai[pp]);
            }
            #pragma unroll 4
            for (int k = 0; k < 64; ++k) {
                float hk = S.hid[j * 64 + k];
                #pragma unroll
                for (int pp = 0; pp < 6; ++pp)
                    ah[pp] = fmaf(hk, S.WhhT[k * 193 + 32 * pp + l], ah[pp]);
            }
            #pragma unroll
            for (int q = 0; q < 2; ++q) {
                int kk = 32 * q + l;
                float rr = sigf(ai[q] + ah[q]);
                float zz = sigf(ai[2 + q] + ah[2 + q]);
                float cd = tanh_acc(fmaf(rr, ah[4 + q], ai[4 + q]));
                float h0 = S.hid[j * 64 + kk];
                S.hid[j * 64 + kk] = cd + zz * (h0 - cd);   // (1-z)*cand + z*h
            }
            __syncwarp();
            // read_gru = hid @ W4^T + b4
            if (l < 8) {
                float v0 = S.b4[l], v1 = 0.f;
                #pragma unroll 8
                for (int k = 0; k < 64; k += 2) {
                    v0 = fmaf(S.hid[j * 64 + k],     S.W4[l * 65 + k],     v0);
                    v1 = fmaf(S.hid[j * 64 + k + 1], S.W4[l * 65 + k + 1], v1);
                }
                S.rg[j * 8 + l] = v0 + v1;
            }
            __syncwarp();
        }
        __syncthreads();
    }

    // ---------------- Final head: p_y_x = ((rg@W3a^T+b3a)@W3b^T+b3b)@W3c^T+b3c ----------------
    {   // stage head weights into now-free WhhT region (coalesced)
        float* st = S.WhhT;
        for (int i = tid; i < 512; i += 256) st[i] = p.W3a[i];
        for (int i = tid; i < 2048; i += 256) st[512 + i] = p.W3b[i];
        if (tid < 128) st[2560 + tid] = p.W3c[tid];
        if (tid < 64)  st[2688 + tid] = p.b3a[tid];
        if (tid < 32)  st[2752 + tid] = p.b3b[tid];
        if (tid < 4)   st[2784 + tid] = p.b3c[tid];
    }
    __syncthreads();
    // t1 = rg @ W3a^T + b3a  -> reuse S.A (flat stride 64)
    for (int i = tid; i < 2048; i += 256) {
        int j = i >> 6, o = i & 63;
        float v = S.WhhT[2688 + o];
        #pragma unroll
        for (int s = 0; s < 8; ++s) v = fmaf(S.rg[j * 8 + s], S.WhhT[o * 8 + s], v);
        S.A[i] = v;
    }
    __syncthreads();
    // t2 = t1 @ W3b^T + b3b -> reuse S.C
    for (int i = tid; i < 1024; i += 256) {
        int j = i >> 5, c = i & 31;
        float v0 = S.WhhT[2752 + c], v1 = 0.f;
        #pragma unroll 8
        for (int k = 0; k < 64; k += 2) {
            v0 = fmaf(S.A[j * 64 + k],     S.WhhT[512 + c * 64 + k],     v0);
            v1 = fmaf(S.A[j * 64 + k + 1], S.WhhT[512 + c * 64 + k + 1], v1);
        }
        S.C[i] = v0 + v1;
    }
    __syncthreads();
    // p_y_x
    if (tid < 128) {
        int j = tid >> 2, o = tid & 3;
        float v = S.WhhT[2784 + o];
        #pragma unroll
        for (int c = 0; c < 32; ++c) v = fmaf(S.C[j * 32 + c], S.WhhT[2560 + o * 32 + c], v);
        p.out[b * 128 + tid] = v;
    }
    // read_gru output
    p.out[p.B * 128 + b * 256 + tid] = S.rg[tid];
    // gru_hidden output
    const int HOFF = p.B * 128 + p.B * 256;
    for (int i = tid; i < 2048; i += 256) p.out[HOFF + b * 2048 + i] = S.hid[i];
}

extern "C" void kernel_launch(void* const* d_in, const int* in_sizes, int n_in,
                              void* d_out, int out_size) {
    Params p;
    p.read_gru = (const float*)d_in[0];
    p.gru_init = (const float*)d_in[1];
    p.feat     = (const float*)d_in[2];
    p.ew       = (const float*)d_in[3];
    p.noise    = (const float*)d_in[4];
    p.xh       = (const float*)d_in[5];
    p.var      = (const float*)d_in[6];
    p.W1a = (const float*)d_in[7];   p.b1a = (const float*)d_in[8];
    p.W2a = (const float*)d_in[9];   p.b2a = (const float*)d_in[10];
    p.W2b = (const float*)d_in[11];  p.b2b = (const float*)d_in[12];
    p.W2c = (const float*)d_in[13];  p.b2c = (const float*)d_in[14];
    p.Wih = (const float*)d_in[15];  p.bih = (const float*)d_in[16];
    p.Whh = (const float*)d_in[17];  p.bhh = (const float*)d_in[18];
    p.W3a = (const float*)d_in[19];  p.b3a = (const float*)d_in[20];
    p.W3b = (const float*)d_in[21];  p.b3b = (const float*)d_in[22];
    p.W3c = (const float*)d_in[23];  p.b3c = (const float*)d_in[24];
    p.W4  = (const float*)d_in[25];  p.b4  = (const float*)d_in[26];
    p.gnn = (const int*)d_in[27];
    p.out = (float*)d_out;
    p.B   = in_sizes[1] / (NN * HHH);   // gru_init is (B, 32, 64)

    const int smem = (int)sizeof(Smem);
    cudaFuncSetAttribute(gnn_kernel, cudaFuncAttributeMaxDynamicSharedMemorySize, smem);
    gnn_kernel<<<p.B, 256, smem, 0>>>(p);
}

// round 4
// speedup vs baseline: 1.2594x; 1.2594x over previous
#include <cuda_runtime.h>

#define NN 32
#define SUU 8
#define HHH 64
#define NCC 4
#define EEE 992
#define NITER 5

typedef unsigned long long ull;

// ---------------- constant-memory weights (warp-uniform reads -> LDCU port) ----
__constant__ __align__(16) float cW2b[32 * 64];  // [c][k]
__constant__ __align__(16) float cW2c[8 * 32];   // [o][c]
__constant__ __align__(16) float cb2b[32];
__constant__ __align__(16) float cb2c[8];

struct __align__(16) Smem {
    // float4/ulonglong2-accessed arrays first (16B alignment, sizes div by 4 floats)
    float A[32 * 68];      // per-node source-part, stride 68 (LDS.128 conflict-free)
    float C[32 * 64];      // per-node target-part + noise + bias
    float Whh3[192 * 68];  // Whh packed per output row g: Whh3[g*68+k]  (also head staging)
    float hid[32 * 64];    // GRU hidden state
    float W4p[8 * 68];     // W4 packed per row, stride 68
    float W2a16[64];       // W2a[:,16] compact (edge-weight column)
    float W2a33[64 * 33];  // W2a rows padded to stride 33 (conflict-free scalar)
    float WihT[10 * 193];  // transposed Wih, stride 193
    float ew[992];
    float inn[32 * 8];
    float rg[32 * 8];
    float xv[64];
    float b2a[64];
    float bih[192];
    float bhh[192];
    float b1a[8];
    float b4[8];
    float W1a[24];
};

struct Params {
    const float* read_gru; const float* gru_init; const float* feat; const float* ew;
    const float* noise; const float* xh; const float* var;
    const float* W1a; const float* b1a;
    const float* W2a; const float* b2a;
    const float* Wih; const float* bih; const float* Whh; const float* bhh;
    const float* W3a; const float* b3a; const float* W3b; const float* b3b;
    const float* W3c; const float* b3c;
    const float* W4; const float* b4;
    const int* gnn;
    float* out;
    int B;
};

__device__ __forceinline__ float sigf(float x) {
    return 1.0f / (1.0f + __expf(-x));
}
__device__ __forceinline__ float tanh_acc(float x) {
    float a = fabsf(x);
    float e = __expf(-2.0f * a);
    float t = (1.0f - e) / (1.0f + e);
    return copysignf(t, x);
}
// packed f32x2 helpers
__device__ __forceinline__ ull pk(float lo, float hi) {
    ull r; asm("mov.b64 %0, {%1,%2};" : "=l"(r) : "f"(lo), "f"(hi)); return r;
}
__device__ __forceinline__ void f2(ull& d, ull a, ull b) {
    asm("fma.rn.f32x2 %0, %1, %2, %0;" : "+l"(d) : "l"(a), "l"(b));
}
__device__ __forceinline__ float2 upk(ull v) {
    float2 r; asm("mov.b64 {%0,%1}, %2;" : "=f"(r.x), "=f"(r.y) : "l"(v)); return r;
}

__global__ void __launch_bounds__(256, 2) gnn_kernel(Params p) {
    extern __shared__ char smem_raw[];
    Smem& S = *reinterpret_cast<Smem*>(smem_raw);
    const int b = blockIdx.x;
    const int tid = threadIdx.x;
    const int w = tid >> 5, l = tid & 31;

    // ---------------- Phase 0: stage into smem ----------------
    for (int i = tid; i < 64 * 18; i += 256) {      // W2a rows -> stride 33
        int o = i / 18, s = i - o * 18;
        S.W2a33[o * 33 + s] = p.W2a[i];
    }
    if (tid < 64) S.W2a16[tid] = p.W2a[tid * 18 + 16];
    for (int i = tid; i < 12288; i += 256) {        // Whh (192,64) -> Whh3[g*68+k]
        int g = i >> 6, k = i & 63;
        S.Whh3[g * 68 + k] = p.Whh[i];
    }
    for (int i = tid; i < 1920; i += 256) {         // Wih (192,10) -> WihT[k][g], stride 193
        int g = i / 10, k = i - g * 10;
        S.WihT[k * 193 + g] = p.Wih[i];
    }
    for (int i = tid; i < 2048; i += 256) S.hid[i] = p.gru_init[b * 2048 + i];
    for (int i = tid; i < 992; i += 256) S.ew[i] = p.ew[b * 992 + i];
    for (int i = tid; i < 512; i += 256) {          // W4 (8,64) -> stride 68
        int s = i >> 6, k = i & 63;
        S.W4p[s * 68 + k] = p.W4[i];
    }
    S.rg[tid] = p.read_gru[b * 256 + tid];
    if (tid < 192) { S.bih[tid] = p.bih[tid]; S.bhh[tid] = p.bhh[tid]; }
    if (tid < 64) S.b2a[tid] = p.b2a[tid];
    if (tid < 32) {
        S.xv[2 * tid]     = p.xh[b * 32 + tid];
        S.xv[2 * tid + 1] = p.var[b * 32 + tid];
    }
    if (tid < 24) S.W1a[tid] = p.W1a[tid];
    if (tid < 8) { S.b1a[tid] = p.b1a[tid]; S.b4[tid] = p.b4[tid]; }
    const float noise = p.noise[b];
    const int gnn = p.gnn[0];
    __syncthreads();

    // ---------------- Main iterations ----------------
    for (int it = 0; it < NITER; ++it) {
        // Phase 1: init_nodes
        {
            int j = tid >> 3, s = tid & 7;
            float v;
            if (it == 0 && gnn == 0) {
                const float* f = p.feat + (b * 32 + j) * 3;
                v = S.b1a[s];
                v = fmaf(f[0], S.W1a[s * 3 + 0], v);
                v = fmaf(f[1], S.W1a[s * 3 + 1], v);
                v = fmaf(f[2], S.W1a[s * 3 + 2], v);
            } else {
                v = S.rg[tid];
            }
            S.inn[tid] = v;
        }
        __syncthreads();

        // Phase 2: per-node A (source part) and C (target part + noise + bias)
        for (int i = tid; i < 2048; i += 256) {
            int a = i >> 6, o = i & 63;
            const float* wr = &S.W2a33[o * 33];
            const float* xn = &S.inn[a * 8];
            float va = 0.f;
            float vc = fmaf(noise, wr[17], S.b2a[o]);
            #pragma unroll
            for (int s = 0; s < 8; ++s) {
                va = fmaf(xn[s], wr[s], va);
                vc = fmaf(xn[s], wr[8 + s], vc);
            }
            S.A[a * 68 + o] = va;
            S.C[a * 64 + o] = vc;
        }
        __syncthreads();

        // Phase 3+4 fused: warp-per-target-node edge MLP + message sum + GRU
        for (int r = 0; r < 4; ++r) {
            const int j = w * 4 + r;
            const bool act = (l < 31);
            int a = l + (l >= j ? 1 : 0);
            if (a > 31) a = 31;
            const float ewv = act ? S.ew[j * 31 + l] : 0.f;

            // layer 1 (factored), vectorized; pack into f32x2 pairs
            ull m1p[32];
            {
                const float4* Cj = reinterpret_cast<const float4*>(&S.C[j * 64]);
                const float4* Aa = reinterpret_cast<const float4*>(&S.A[a * 68]);
                const float4* Wc = reinterpret_cast<const float4*>(S.W2a16);
                #pragma unroll
                for (int o4 = 0; o4 < 16; ++o4) {
                    float4 c4 = Cj[o4], a4 = Aa[o4], w4 = Wc[o4];
                    float p0 = fmaxf(fmaf(ewv, w4.x, c4.x) + a4.x, 0.f);
                    float p1 = fmaxf(fmaf(ewv, w4.y, c4.y) + a4.y, 0.f);
                    float p2 = fmaxf(fmaf(ewv, w4.z, c4.z) + a4.z, 0.f);
                    float p3 = fmaxf(fmaf(ewv, w4.w, c4.w) + a4.w, 0.f);
                    m1p[2 * o4]     = pk(p0, p1);
                    m1p[2 * o4 + 1] = pk(p2, p3);
                }
            }

            // layers 2+3 (weights from constant memory; f32x2, c processed in pairs)
            ull accp[8];
            #pragma unroll
            for (int o = 0; o < 8; ++o) accp[o] = 0ull;
            #pragma unroll 1
            for (int c = 0; c < 32; c += 2) {
                const ulonglong2* wpe = reinterpret_cast<const ulonglong2*>(cW2b + c * 64);
                const ulonglong2* wpo = reinterpret_cast<const ulonglong2*>(cW2b + (c + 1) * 64);
                ull s0 = 0ull, s1 = 0ull, r0 = 0ull, r1 = 0ull;
                #pragma unroll
                for (int k4 = 0; k4 < 16; ++k4) {
                    ulonglong2 we = wpe[k4];
                    ulonglong2 wo = wpo[k4];
                    ull ma = m1p[2 * k4], mb = m1p[2 * k4 + 1];
                    f2(s0, ma, we.x); f2(s1, mb, we.y);
                    f2(r0, ma, wo.x); f2(r1, mb, wo.y);
                }
                float2 e0 = upk(s0), e1 = upk(s1), o0 = upk(r0), o1 = upk(r1);
                float te = fmaxf(cb2b[c]     + (e0.x + e0.y) + (e1.x + e1.y), 0.f);
                float to = fmaxf(cb2b[c + 1] + (o0.x + o0.y) + (o1.x + o1.y), 0.f);
                ull tt = pk(te, to);
                const ull* up = reinterpret_cast<const ull*>(cW2c);
                #pragma unroll
                for (int o = 0; o < 8; ++o)
                    f2(accp[o], tt, up[(o * 32 + c) >> 1]);
            }
            float acc[8];
            #pragma unroll
            for (int o = 0; o < 8; ++o) {
                float2 v = upk(accp[o]);
                acc[o] = act ? fmaxf(cb2c[o] + v.x + v.y, 0.f) : 0.f;
            }

            // butterfly sum over edges
            #pragma unroll
            for (int off = 16; off >= 1; off >>= 1) {
                #pragma unroll
                for (int o = 0; o < 8; ++o)
                    acc[o] += __shfl_xor_sync(0xFFFFFFFFu, acc[o], off);
            }

            // ---- GRU for node j (lane l owns channels g = 32p + l) ----
            const float xh = S.xv[2 * j], vv = S.xv[2 * j + 1];
            float ai[6];
            #pragma unroll
            for (int pp = 0; pp < 6; ++pp) ai[pp] = S.bih[32 * pp + l];
            #pragma unroll
            for (int k = 0; k < 8; ++k) {
                float g = acc[k];
                #pragma unroll
                for (int pp = 0; pp < 6; ++pp)
                    ai[pp] = fmaf(g, S.WihT[k * 193 + 32 * pp + l], ai[pp]);
            }
            #pragma unroll
            for (int pp = 0; pp < 6; ++pp) {
                ai[pp] = fmaf(xh, S.WihT[8 * 193 + 32 * pp + l], ai[pp]);
                ai[pp] = fmaf(vv, S.WihT[9 * 193 + 32 * pp + l], ai[pp]);
            }
            // Whh matvec: packed rows, LDS.128 conflict-free (stride 68 == 4 mod 32)
            ull ahp[6];
            #pragma unroll
            for (int pp = 0; pp < 6; ++pp) ahp[pp] = 0ull;
            {
                const ulonglong2* hp2 = reinterpret_cast<const ulonglong2*>(&S.hid[j * 64]);
                const ulonglong2* wb  = reinterpret_cast<const ulonglong2*>(S.Whh3) + l * 17;
                #pragma unroll
                for (int k4 = 0; k4 < 16; ++k4) {
                    ulonglong2 h2 = hp2[k4];
                    #pragma unroll
                    for (int pp = 0; pp < 6; ++pp) {
                        ulonglong2 wv = wb[pp * 544 + k4];
                        f2(ahp[pp], h2.x, wv.x);
                        f2(ahp[pp], h2.y, wv.y);
                    }
                }
            }
            #pragma unroll
            for (int q = 0; q < 2; ++q) {
                int kk = 32 * q + l;
                float2 vr = upk(ahp[q]);
                float2 vz = upk(ahp[2 + q]);
                float2 vn = upk(ahp[4 + q]);
                float ahr = S.bhh[32 * q + l]        + vr.x + vr.y;
                float ahz = S.bhh[32 * (2 + q) + l]  + vz.x + vz.y;
                float ahn = S.bhh[32 * (4 + q) + l]  + vn.x + vn.y;
                float rr = sigf(ai[q] + ahr);
                float zz = sigf(ai[2 + q] + ahz);
                float cd = tanh_acc(fmaf(rr, ahn, ai[4 + q]));
                float h0 = S.hid[j * 64 + kk];
                S.hid[j * 64 + kk] = cd + zz * (h0 - cd);
            }
            __syncwarp();
            // read_gru = hid @ W4^T + b4 (vectorized)
            if (l < 8) {
                const float4* wp = reinterpret_cast<const float4*>(&S.W4p[l * 68]);
                const float4* hp = reinterpret_cast<const float4*>(&S.hid[j * 64]);
                float v0 = S.b4[l], v1 = 0.f, v2 = 0.f, v3 = 0.f;
                #pragma unroll
                for (int k4 = 0; k4 < 16; ++k4) {
                    float4 ww = wp[k4];
                    float4 hh = hp[k4];
                    v0 = fmaf(hh.x, ww.x, v0);
                    v1 = fmaf(hh.y, ww.y, v1);
                    v2 = fmaf(hh.z, ww.z, v2);
                    v3 = fmaf(hh.w, ww.w, v3);
                }
                S.rg[j * 8 + l] = (v0 + v1) + (v2 + v3);
            }
            __syncwarp();
        }
        __syncthreads();
    }

    // ---------------- Final head ----------------
    {   // stage head weights into now-free Whh3 region
        float* st = S.Whh3;
        for (int i = tid; i < 512; i += 256) st[i] = p.W3a[i];
        for (int i = tid; i < 2048; i += 256) st[512 + i] = p.W3b[i];
        if (tid < 128) st[2560 + tid] = p.W3c[tid];
        if (tid < 64)  st[2688 + tid] = p.b3a[tid];
        if (tid < 32)  st[2752 + tid] = p.b3b[tid];
        if (tid < 4)   st[2784 + tid] = p.b3c[tid];
    }
    __syncthreads();
    // t1 = rg @ W3a^T + b3a -> reuse S.A (flat)
    for (int i = tid; i < 2048; i += 256) {
        int j = i >> 6, o = i & 63;
        float v = S.Whh3[2688 + o];
        #pragma unroll
        for (int s = 0; s < 8; ++s) v = fmaf(S.rg[j * 8 + s], S.Whh3[o * 8 + s], v);
        S.A[i] = v;
    }
    __syncthreads();
    // t2 = t1 @ W3b^T + b3b -> reuse S.C
    for (int i = tid; i < 1024; i += 256) {
        int j = i >> 5, c = i & 31;
        float v0 = S.Whh3[2752 + c], v1 = 0.f;
        #pragma unroll 8
        for (int k = 0; k < 64; k += 2) {
            v0 = fmaf(S.A[j * 64 + k],     S.Whh3[512 + c * 64 + k],     v0);
            v1 = fmaf(S.A[j * 64 + k + 1], S.Whh3[512 + c * 64 + k + 1], v1);
        }
        S.C[i] = v0 + v1;
    }
    __syncthreads();
    // p_y_x
    if (tid < 128) {
        int j = tid >> 2, o = tid & 3;
        float v = S.Whh3[2784 + o];
        #pragma unroll
        for (int c = 0; c < 32; ++c) v = fmaf(S.C[j * 32 + c], S.Whh3[2560 + o * 32 + c], v);
        p.out[b * 128 + tid] = v;
    }
    // read_gru output
    p.out[p.B * 128 + b * 256 + tid] = S.rg[tid];
    // gru_hidden output
    const int HOFF = p.B * 128 + p.B * 256;
    for (int i = tid; i < 2048; i += 256) p.out[HOFF + b * 2048 + i] = S.hid[i];
}

extern "C" void kernel_launch(void* const* d_in, const int* in_sizes, int n_in,
                              void* d_out, int out_size) {
    Params p;
    p.read_gru = (const float*)d_in[0];
    p.gru_init = (const float*)d_in[1];
    p.feat     = (const float*)d_in[2];
    p.ew       = (const float*)d_in[3];
    p.noise    = (const float*)d_in[4];
    p.xh       = (const float*)d_in[5];
    p.var      = (const float*)d_in[6];
    p.W1a = (const float*)d_in[7];   p.b1a = (const float*)d_in[8];
    p.W2a = (const float*)d_in[9];
    const float* W2a_b2a = (const float*)d_in[10];
    p.b2a = W2a_b2a;
    p.Wih = (const float*)d_in[15];  p.bih = (const float*)d_in[16];
    p.Whh = (const float*)d_in[17];  p.bhh = (const float*)d_in[18];
    p.W3a = (const float*)d_in[19];  p.b3a = (const float*)d_in[20];
    p.W3b = (const float*)d_in[21];  p.b3b = (const float*)d_in[22];
    p.W3c = (const float*)d_in[23];  p.b3c = (const float*)d_in[24];
    p.W4  = (const float*)d_in[25];  p.b4  = (const float*)d_in[26];
    p.gnn = (const int*)d_in[27];
    p.out = (float*)d_out;
    p.B   = in_sizes[1] / (NN * HHH);   // gru_init is (B, 32, 64)

    // warp-uniform weights -> constant memory (D2D async copies; graph-capturable)
    cudaMemcpyToSymbolAsync(cW2b, d_in[11], 32 * 64 * sizeof(float), 0,
                            cudaMemcpyDeviceToDevice, 0);
    cudaMemcpyToSymbolAsync(cb2b, d_in[12], 32 * sizeof(float), 0,
                            cudaMemcpyDeviceToDevice, 0);
    cudaMemcpyToSymbolAsync(cW2c, d_in[13], 8 * 32 * sizeof(float), 0,
                            cudaMemcpyDeviceToDevice, 0);
    cudaMemcpyToSymbolAsync(cb2c, d_in[14], 8 * sizeof(float), 0,
                            cudaMemcpyDeviceToDevice, 0);

    const int smem = (int)sizeof(Smem);
    cudaFuncSetAttribute(gnn_kernel, cudaFuncAttributeMaxDynamicSharedMemorySize, smem);
    gnn_kernel<<<p.B, 256, smem, 0>>>(p);
}